// round 15
// baseline (speedup 1.0000x reference)
#include <cuda_runtime.h>
#include <cstdint>

// Problem constants
#define NN 1024
#define DD 64
#define RR 32
#define NEGV (-1e14f)

// Scratch / accumulators (no device allocation allowed).
// Zero-initialized at load; the last k_ewm block consumes and re-zeroes them,
// so every kernel_launch call (and every graph replay) starts from the same state.
__device__ float g_ewm[(size_t)NN * NN];
__device__ double g_sum;
__device__ double g_sumsq;
__device__ unsigned long long g_cnt;
__device__ unsigned int g_done;
__device__ float g_mean;
__device__ float g_invstd;

// L2 access policies (sm_80+). Direct .L2::evict_* modifiers need 256-bit
// types on sm_103a ptxas; the createpolicy + cache_hint form works at any width.
__device__ __forceinline__ uint64_t pol_evict_last() {
    uint64_t pol;
    asm("createpolicy.fractional.L2::evict_last.b64 %0, 1.0;" : "=l"(pol));
    return pol;
}
__device__ __forceinline__ uint64_t pol_evict_first() {
    uint64_t pol;
    asm("createpolicy.fractional.L2::evict_first.b64 %0, 1.0;" : "=l"(pol));
    return pol;
}

// Store float4 with L2 evict-last priority: pins g_ewm lines in L2 so the
// 512MB grad/rs evict-normal stream doesn't flush them before k_out rereads.
__device__ __forceinline__ void st_evict_last4(float* p, float4 v, uint64_t pol) {
    asm volatile("st.global.L2::cache_hint.v4.f32 [%0], {%1,%2,%3,%4}, %5;"
                 :: "l"(p), "f"(v.x), "f"(v.y), "f"(v.z), "f"(v.w), "l"(pol) : "memory");
}

// Load float with L2 evict-first (last use of g_ewm — free the line).
__device__ __forceinline__ float ld_evict_first(const float* p, uint64_t pol) {
    float v;
    asm volatile("ld.global.L2::cache_hint.f32 %0, [%1], %2;"
                 : "=f"(v) : "l"(p), "l"(pol));
    return v;
}

// ewm[i,j] = sum_d grad[i,j,d] * rs[j,i,d]
// Block = 16x16 pair tile for DRAM locality on the transposed rs reads.
// 8 lanes per pair, float4 plain loads (evict-normal: fastest for the pure
// stream; g_ewm is protected by evict-last stores instead). 2-deep software
// pipeline: both pair-groups' 8 LDG.128 issued before any shuffle reduction.
// Stats (mean / unbiased std over nonzero ewm) are finished by the last
// block to arrive (ticket pattern) — no separate kernel.
__global__ void k_ewm(const float* __restrict__ grad,
                      const float* __restrict__ rs) {
    __shared__ double s_sum[8], s_ss[8];
    __shared__ unsigned int s_cnt[8];

    const int tid  = threadIdx.x;
    const int w    = tid >> 5;
    const int lane = tid & 31;
    const int pg   = lane >> 3;   // pair within warp (0..3)
    const int sub  = lane & 7;    // chunk within pair (0..7)

    const int i0 = blockIdx.y << 4;
    const int j0 = blockIdx.x << 4;

    const uint64_t polL = pol_evict_last();

    float ls = 0.0f, lss = 0.0f;
    unsigned int lc = 0u;

    #pragma unroll
    for (int t = 0; t < 8; t += 2) {
        // ---- addresses for both groups ----
        const int gA = t * 8 + w;
        const int gB = gA + 8;
        const int iA  = i0 + (gA >> 2);
        const int jbA = j0 + ((gA & 3) << 2);
        const int iB  = i0 + (gB >> 2);
        const int jbB = j0 + ((gB & 3) << 2);

        const float4* gaA = (const float4*)(grad + (((size_t)iA << 10) + jbA + pg) * DD);
        const float4* raA = (const float4*)(rs   + (((size_t)(jbA + pg) << 10) + iA) * DD);
        const float4* gaB = (const float4*)(grad + (((size_t)iB << 10) + jbB + pg) * DD);
        const float4* raB = (const float4*)(rs   + (((size_t)(jbB + pg) << 10) + iB) * DD);

        // ---- issue all 8 loads up front ----
        float4 Ag0 = gaA[sub];
        float4 Ag1 = gaA[sub + 8];
        float4 Ar0 = raA[sub];
        float4 Ar1 = raA[sub + 8];
        float4 Bg0 = gaB[sub];
        float4 Bg1 = gaB[sub + 8];
        float4 Br0 = raB[sub];
        float4 Br1 = raB[sub + 8];

        // ---- group A ----
        float accA = Ag0.x * Ar0.x + Ag0.y * Ar0.y + Ag0.z * Ar0.z + Ag0.w * Ar0.w
                   + Ag1.x * Ar1.x + Ag1.y * Ar1.y + Ag1.z * Ar1.z + Ag1.w * Ar1.w;
        accA += __shfl_xor_sync(0xffffffffu, accA, 4);
        accA += __shfl_xor_sync(0xffffffffu, accA, 2);
        accA += __shfl_xor_sync(0xffffffffu, accA, 1);

        float a0 = __shfl_sync(0xffffffffu, accA, 0);
        float a1 = __shfl_sync(0xffffffffu, accA, 8);
        float a2 = __shfl_sync(0xffffffffu, accA, 16);
        float a3 = __shfl_sync(0xffffffffu, accA, 24);
        if (lane == 0)
            st_evict_last4(g_ewm + ((size_t)iA << 10) + jbA,
                           make_float4(a0, a1, a2, a3), polL);
        if (sub == 0 && accA != 0.0f) { ls += accA; lss += accA * accA; lc += 1u; }

        // ---- group B ----
        float accB = Bg0.x * Br0.x + Bg0.y * Br0.y + Bg0.z * Br0.z + Bg0.w * Br0.w
                   + Bg1.x * Br1.x + Bg1.y * Br1.y + Bg1.z * Br1.z + Bg1.w * Br1.w;
        accB += __shfl_xor_sync(0xffffffffu, accB, 4);
        accB += __shfl_xor_sync(0xffffffffu, accB, 2);
        accB += __shfl_xor_sync(0xffffffffu, accB, 1);

        float b0 = __shfl_sync(0xffffffffu, accB, 0);
        float b1 = __shfl_sync(0xffffffffu, accB, 8);
        float b2 = __shfl_sync(0xffffffffu, accB, 16);
        float b3 = __shfl_sync(0xffffffffu, accB, 24);
        if (lane == 0)
            st_evict_last4(g_ewm + ((size_t)iB << 10) + jbB,
                           make_float4(b0, b1, b2, b3), polL);
        if (sub == 0 && accB != 0.0f) { ls += accB; lss += accB * accB; lc += 1u; }
    }

    // warp reduce (only lanes with sub==0 carry data; others are zero)
    #pragma unroll
    for (int off = 16; off > 0; off >>= 1) {
        ls  += __shfl_xor_sync(0xffffffffu, ls, off);
        lss += __shfl_xor_sync(0xffffffffu, lss, off);
        lc  += __shfl_xor_sync(0xffffffffu, lc, off);
    }
    if (lane == 0) { s_sum[w] = (double)ls; s_ss[w] = (double)lss; s_cnt[w] = lc; }
    __syncthreads();
    if (tid == 0) {
        double bs = 0.0, bss = 0.0;
        unsigned int bc = 0u;
        #pragma unroll
        for (int k = 0; k < 8; ++k) { bs += s_sum[k]; bss += s_ss[k]; bc += s_cnt[k]; }
        if (bc) {
            atomicAdd(&g_sum, bs);
            atomicAdd(&g_sumsq, bss);
            atomicAdd(&g_cnt, (unsigned long long)bc);
        }
        __threadfence();
        const unsigned int total = gridDim.x * gridDim.y;
        unsigned int ticket = atomicAdd(&g_done, 1u);
        if (ticket == total - 1) {
            // all blocks' accumulator updates are visible now
            double c    = (double)g_cnt;
            double mean = g_sum / c;
            double var  = (g_sumsq - g_sum * g_sum / c) / (c - 1.0);
            g_mean   = (float)mean;
            g_invstd = (float)(1.0 / sqrt(var));
            // reset for the next graph replay
            g_sum = 0.0;
            g_sumsq = 0.0;
            g_cnt = 0ull;
            g_done = 0u;
            __threadfence();
        }
    }
}

// Softmax/scale for one 4-value slice of a pair. 8-lane-group reductions.
__device__ __forceinline__ void out_pair(float4 m, float4 mg, float ew,
                                         float mean, float invstd,
                                         float4& o) {
    float4 g = make_float4(m.x * mg.x, m.y * mg.y, m.z * mg.z, m.w * mg.w);

    float mx = fmaxf(fmaxf(g.x, g.y), fmaxf(g.z, g.w));
    float mn = fminf(fminf(g.x, g.y), fminf(g.z, g.w));
    #pragma unroll
    for (int off = 4; off > 0; off >>= 1) {
        mx = fmaxf(mx, __shfl_xor_sync(0xffffffffu, mx, off));
        mn = fminf(mn, __shfl_xor_sync(0xffffffffu, mn, off));
    }

    const float inv2 = 2.0f / (mx - mn);   // inf if all-zero; e's selected to 0 below

    float e0 = (g.x == 0.0f) ? 0.0f : __expf(fmaf(g.x - mn, inv2, -1.0f));
    float e1 = (g.y == 0.0f) ? 0.0f : __expf(fmaf(g.y - mn, inv2, -1.0f));
    float e2 = (g.z == 0.0f) ? 0.0f : __expf(fmaf(g.z - mn, inv2, -1.0f));
    float e3 = (g.w == 0.0f) ? 0.0f : __expf(fmaf(g.w - mn, inv2, -1.0f));

    float s = (e0 + e1) + (e2 + e3);
    #pragma unroll
    for (int off = 4; off > 0; off >>= 1)
        s += __shfl_xor_sync(0xffffffffu, s, off);

    const float invs = (s > 0.0f) ? (1.0f / s) : 0.0f;

    float sig = 0.0f;
    if (ew != 0.0f)
        sig = 1.0f / (1.0f + __expf(-(ew - mean) * invstd));

    const float f = sig * invs;
    o = make_float4(e0 * m.x * f, e1 * m.y * f, e2 * m.z * f, e3 * m.w * f);
}

// Fused epilogue: each warp handles 8 pairs as two independent 512B-contiguous
// float4 sets, loaded back-to-back before compute for doubled MLP. g_ewm is
// read first (L2-resident via evict_last pin) with evict_first since it's the
// last use of those lines.
__global__ void k_out(const float* __restrict__ rm,
                      const float* __restrict__ rmg,
                      float* __restrict__ out) {
    const int lane = threadIdx.x & 31;
    const int pg   = lane >> 3;
    const int W    = (blockIdx.x * blockDim.x + threadIdx.x) >> 5;

    const size_t b0 = (size_t)W * 64 + lane;   // float4 idx, set A (pairs 8W..8W+3)
    const size_t b1 = b0 + 32;                 // set B (pairs 8W+4..8W+7)
    const int pA = W * 8 + pg;
    const int pB = pA + 4;

    const uint64_t polF = pol_evict_first();

    // issue all loads first (MLP); ewm first (L2 hit expected)
    float ewA = ld_evict_first(g_ewm + pA, polF);
    float ewB = ld_evict_first(g_ewm + pB, polF);
    float4 mA  = __ldcs(((const float4*)rm)  + b0);
    float4 gA  = __ldcs(((const float4*)rmg) + b0);
    float4 mB  = __ldcs(((const float4*)rm)  + b1);
    float4 gB  = __ldcs(((const float4*)rmg) + b1);

    const float mean   = g_mean;
    const float invstd = g_invstd;

    float4 oA, oB;
    out_pair(mA, gA, ewA, mean, invstd, oA);
    out_pair(mB, gB, ewB, mean, invstd, oB);

    __stcs(((float4*)out) + b0, oA);
    __stcs(((float4*)out) + b1, oB);
}

extern "C" void kernel_launch(void* const* d_in, const int* in_sizes, int n_in,
                              void* d_out, int out_size) {
    const float* rs   = (const float*)d_in[0];  // relation_stocks [N,N,D]
    const float* grad = (const float*)d_in[1];  // grad            [N,N,D]
    const float* rm   = (const float*)d_in[2];  // relation_matrix [N,N,R]
    const float* rmg  = (const float*)d_in[3];  // relation_matrix_grad [N,N,R]
    float* out = (float*)d_out;                 // [N,N,R]

    (void)in_sizes; (void)n_in; (void)out_size;

    k_ewm<<<dim3(64, 64), 256>>>(grad, rs);
    // 1M pairs / (8 pairs/warp * 8 warps/block) = 16384 blocks
    k_out<<<16384, 256>>>(rm, rmg, out);
}

// round 16
// speedup vs baseline: 1.0310x; 1.0310x over previous
#include <cuda_runtime.h>

// Problem constants
#define NN 1024
#define DD 64
#define RR 32
#define NEGV (-1e14f)

// Scratch / accumulators (no device allocation allowed).
// Zero-initialized at load; the last k_ewm block consumes and re-zeroes them,
// so every kernel_launch call (and every graph replay) starts from the same state.
__device__ float g_ewm[(size_t)NN * NN];
__device__ double g_sum;
__device__ double g_sumsq;
__device__ unsigned long long g_cnt;
__device__ unsigned int g_done;
__device__ float g_mean;
__device__ float g_invstd;

// ewm[i,j] = sum_d grad[i,j,d] * rs[j,i,d]
// Block = 16x16 pair tile for DRAM locality on the transposed rs reads.
// 8 lanes per pair, float4 __ldcs loads (evict-first: the 512MB stream must
// not evict the freshly written 4MB g_ewm from L2 — k_out rereads it).
// 4-deep software pipeline: four pair-groups' 16 LDG.128 issued before any
// shuffle reduction. Stats (mean / unbiased std over nonzero ewm) are
// finished by the last block to arrive (ticket pattern) — no separate kernel.
__global__ void k_ewm(const float* __restrict__ grad,
                      const float* __restrict__ rs) {
    __shared__ double s_sum[8], s_ss[8];
    __shared__ unsigned int s_cnt[8];

    const int tid  = threadIdx.x;
    const int w    = tid >> 5;
    const int lane = tid & 31;
    const int pg   = lane >> 3;   // pair within warp (0..3)
    const int sub  = lane & 7;    // chunk within pair (0..7)

    const int i0 = blockIdx.y << 4;
    const int j0 = blockIdx.x << 4;

    float ls = 0.0f, lss = 0.0f;
    unsigned int lc = 0u;

    #pragma unroll
    for (int t = 0; t < 2; ++t) {
        // ---- group ids: g = t*32 + w + {0,8,16,24} covers 0..63 ----
        int gi[4], gj[4];
        const float4* gp[4];
        const float4* rp[4];
        #pragma unroll
        for (int q = 0; q < 4; ++q) {
            const int g = t * 32 + q * 8 + w;
            const int i  = i0 + (g >> 2);
            const int jb = j0 + ((g & 3) << 2);
            gi[q] = i;
            gj[q] = jb;
            gp[q] = (const float4*)(grad + (((size_t)i << 10) + jb + pg) * DD);
            rp[q] = (const float4*)(rs   + (((size_t)(jb + pg) << 10) + i) * DD);
        }

        // ---- issue all 16 loads up front (evict-first) ----
        float4 G0[4], G1[4], R0[4], R1[4];
        #pragma unroll
        for (int q = 0; q < 4; ++q) {
            G0[q] = __ldcs(gp[q] + sub);
            G1[q] = __ldcs(gp[q] + sub + 8);
            R0[q] = __ldcs(rp[q] + sub);
            R1[q] = __ldcs(rp[q] + sub + 8);
        }

        // ---- reduce each group ----
        #pragma unroll
        for (int q = 0; q < 4; ++q) {
            float acc = G0[q].x * R0[q].x + G0[q].y * R0[q].y
                      + G0[q].z * R0[q].z + G0[q].w * R0[q].w
                      + G1[q].x * R1[q].x + G1[q].y * R1[q].y
                      + G1[q].z * R1[q].z + G1[q].w * R1[q].w;
            acc += __shfl_xor_sync(0xffffffffu, acc, 4);
            acc += __shfl_xor_sync(0xffffffffu, acc, 2);
            acc += __shfl_xor_sync(0xffffffffu, acc, 1);

            float a0 = __shfl_sync(0xffffffffu, acc, 0);
            float a1 = __shfl_sync(0xffffffffu, acc, 8);
            float a2 = __shfl_sync(0xffffffffu, acc, 16);
            float a3 = __shfl_sync(0xffffffffu, acc, 24);
            if (lane == 0)
                *(float4*)(g_ewm + ((size_t)gi[q] << 10) + gj[q]) =
                    make_float4(a0, a1, a2, a3);
            if (sub == 0 && acc != 0.0f) { ls += acc; lss += acc * acc; lc += 1u; }
        }
    }

    // warp reduce (only lanes with sub==0 carry data; others are zero)
    #pragma unroll
    for (int off = 16; off > 0; off >>= 1) {
        ls  += __shfl_xor_sync(0xffffffffu, ls, off);
        lss += __shfl_xor_sync(0xffffffffu, lss, off);
        lc  += __shfl_xor_sync(0xffffffffu, lc, off);
    }
    if (lane == 0) { s_sum[w] = (double)ls; s_ss[w] = (double)lss; s_cnt[w] = lc; }
    __syncthreads();
    if (tid == 0) {
        double bs = 0.0, bss = 0.0;
        unsigned int bc = 0u;
        #pragma unroll
        for (int k = 0; k < 8; ++k) { bs += s_sum[k]; bss += s_ss[k]; bc += s_cnt[k]; }
        if (bc) {
            atomicAdd(&g_sum, bs);
            atomicAdd(&g_sumsq, bss);
            atomicAdd(&g_cnt, (unsigned long long)bc);
        }
        __threadfence();
        const unsigned int total = gridDim.x * gridDim.y;
        unsigned int ticket = atomicAdd(&g_done, 1u);
        if (ticket == total - 1) {
            // all blocks' accumulator updates are visible now
            double c    = (double)g_cnt;
            double mean = g_sum / c;
            double var  = (g_sumsq - g_sum * g_sum / c) / (c - 1.0);
            g_mean   = (float)mean;
            g_invstd = (float)(1.0 / sqrt(var));
            // reset for the next graph replay
            g_sum = 0.0;
            g_sumsq = 0.0;
            g_cnt = 0ull;
            g_done = 0u;
            __threadfence();
        }
    }
}

// Softmax/scale for one 4-value slice of a pair. 8-lane-group reductions.
__device__ __forceinline__ void out_pair(float4 m, float4 mg, float ew,
                                         float mean, float invstd,
                                         float4& o) {
    float4 g = make_float4(m.x * mg.x, m.y * mg.y, m.z * mg.z, m.w * mg.w);

    float mx = fmaxf(fmaxf(g.x, g.y), fmaxf(g.z, g.w));
    float mn = fminf(fminf(g.x, g.y), fminf(g.z, g.w));
    #pragma unroll
    for (int off = 4; off > 0; off >>= 1) {
        mx = fmaxf(mx, __shfl_xor_sync(0xffffffffu, mx, off));
        mn = fminf(mn, __shfl_xor_sync(0xffffffffu, mn, off));
    }

    const float inv2 = 2.0f / (mx - mn);   // inf if all-zero; e's selected to 0 below

    float e0 = (g.x == 0.0f) ? 0.0f : __expf(fmaf(g.x - mn, inv2, -1.0f));
    float e1 = (g.y == 0.0f) ? 0.0f : __expf(fmaf(g.y - mn, inv2, -1.0f));
    float e2 = (g.z == 0.0f) ? 0.0f : __expf(fmaf(g.z - mn, inv2, -1.0f));
    float e3 = (g.w == 0.0f) ? 0.0f : __expf(fmaf(g.w - mn, inv2, -1.0f));

    float s = (e0 + e1) + (e2 + e3);
    #pragma unroll
    for (int off = 4; off > 0; off >>= 1)
        s += __shfl_xor_sync(0xffffffffu, s, off);

    const float invs = (s > 0.0f) ? (1.0f / s) : 0.0f;

    float sig = 0.0f;
    if (ew != 0.0f)
        sig = 1.0f / (1.0f + __expf(-(ew - mean) * invstd));

    const float f = sig * invs;
    o = make_float4(e0 * m.x * f, e1 * m.y * f, e2 * m.z * f, e3 * m.w * f);
}

// Fused epilogue: each warp handles 16 pairs as four independent
// 512B-contiguous float4 sets, all loads issued before compute (4x MLP).
// g_ewm (L2-resident thanks to k_ewm's __ldcs stream) is read first.
__global__ void k_out(const float* __restrict__ rm,
                      const float* __restrict__ rmg,
                      float* __restrict__ out) {
    const int lane = threadIdx.x & 31;
    const int pg   = lane >> 3;
    const int W    = (blockIdx.x * blockDim.x + threadIdx.x) >> 5;

    const size_t base = (size_t)W * 128 + lane;  // float4 idx of set 0
    const int p0 = W * 16 + pg;

    // issue all loads first (MLP); ewm first to hide any L2 miss
    float ew[4];
    #pragma unroll
    for (int q = 0; q < 4; ++q) ew[q] = g_ewm[p0 + q * 4];

    float4 M[4], G[4];
    #pragma unroll
    for (int q = 0; q < 4; ++q) {
        M[q] = __ldcs(((const float4*)rm)  + base + q * 32);
        G[q] = __ldcs(((const float4*)rmg) + base + q * 32);
    }

    const float mean   = g_mean;
    const float invstd = g_invstd;

    #pragma unroll
    for (int q = 0; q < 4; ++q) {
        float4 o;
        out_pair(M[q], G[q], ew[q], mean, invstd, o);
        __stcs(((float4*)out) + base + q * 32, o);
    }
}

extern "C" void kernel_launch(void* const* d_in, const int* in_sizes, int n_in,
                              void* d_out, int out_size) {
    const float* rs   = (const float*)d_in[0];  // relation_stocks [N,N,D]
    const float* grad = (const float*)d_in[1];  // grad            [N,N,D]
    const float* rm   = (const float*)d_in[2];  // relation_matrix [N,N,R]
    const float* rmg  = (const float*)d_in[3];  // relation_matrix_grad [N,N,R]
    float* out = (float*)d_out;                 // [N,N,R]

    (void)in_sizes; (void)n_in; (void)out_size;

    k_ewm<<<dim3(64, 64), 256>>>(grad, rs);
    // 1M pairs / (16 pairs/warp * 8 warps/block) = 8192 blocks
    k_out<<<8192, 256>>>(rm, rmg, out);
}